// round 1
// baseline (speedup 1.0000x reference)
#include <cuda_runtime.h>
#include <cstdint>

#define NDOM 4
#define NB   8192
#define NF   128
#define BM   128
#define BN   128
#define NTHREADS 256
#define SMEM_BYTES ((2 * BM * NF) * 4 + BN * 4)

// Scratch for normalized int32 labels (no cudaMalloc allowed).
__device__ int g_labels[NDOM * NB];

// Labels may arrive as int64 or int32 (JAX x64 flag dependent). Values are in
// [0, 64). If int64 (little-endian, non-negative), every odd 32-bit word is 0.
// For random int32 labels the odd words are random -> detection is unambiguous.
__global__ void convert_labels_kernel(const unsigned int* __restrict__ w, int n) {
    __shared__ int s_any;
    if (threadIdx.x == 0) s_any = 0;
    __syncthreads();
    int any = 0;
    for (int i = threadIdx.x; i < n / 2; i += blockDim.x)
        any |= (w[2 * i + 1] != 0u);  // stays within n words even if int32
    if (any) atomicOr(&s_any, 1);
    __syncthreads();
    const bool is64 = (s_any == 0);
    for (int i = threadIdx.x; i < n; i += blockDim.x)
        g_labels[i] = is64 ? (int)w[2 * i] : (int)w[i];
}

// Cooperative tile loader: gmem [128 rows x 128 floats] row-major ->
// smem k-major [k][x] with XOR swizzle x' = x ^ (4*((k>>2)&7)).
// Per warp-step: 4 rows x 32 floats (coalesced 4x128B reads, conflict-free STS).
__device__ __forceinline__ void load_tile(float* __restrict__ dst,
                                          const float* __restrict__ src,
                                          int tid) {
    const int lane = tid & 31, warp = tid >> 5;
    const int jo = lane & 3;        // row offset 0..3
    const int ko = lane >> 2;       // chunk 0..7
#pragma unroll
    for (int it = 0; it < 16; ++it) {
        const int seg = it * 8 + warp;       // 0..127
        const int rb  = (seg >> 2) << 2;     // row base (mult of 4)
        const int q   = seg & 3;             // quarter of the row
        const int row = rb + jo;
        const int k0  = q * 32 + ko * 4;
        float4 v = *reinterpret_cast<const float4*>(src + (size_t)row * NF + k0);
        const int xj = row ^ (ko << 2);      // (k0>>2)&7 == ko
        dst[(k0 + 0) * BM + xj] = v.x;
        dst[(k0 + 1) * BM + xj] = v.y;
        dst[(k0 + 2) * BM + xj] = v.z;
        dst[(k0 + 3) * BM + xj] = v.w;
    }
}

__global__ __launch_bounds__(NTHREADS, 1)
void mine_kernel(const float* __restrict__ emb,
                 float* __restrict__ pos_dist, float* __restrict__ neg_dist,
                 float* __restrict__ pos_embed, float* __restrict__ neg_embed) {
    extern __shared__ float smem[];
    float* sA = smem;                  // 128x128 swizzled
    float* sB = smem + BM * NF;        // 128x128 swizzled
    int*   sLab = (int*)(smem + 2 * BM * NF);  // 128 labels of current j-tile

    const int tid = threadIdx.x;
    const int tx = tid & 15;           // col thread  (0..15)
    const int ty = tid >> 4;           // row thread  (0..15)
    const int d  = blockIdx.y;
    const int tb = blockIdx.x * BM;    // row-tile base within domain

    const float* __restrict__ embd = emb + (size_t)d * NB * NF;
    const int*   __restrict__ labd = g_labels + d * NB;

    // A tile (rows tb..tb+127), resident for whole kernel.
    load_tile(sA, embd + (size_t)tb * NF, tid);

    // Row labels for this thread's 8 rows: {p*64 + ty*4 + r}.
    int li[2][4];
#pragma unroll
    for (int p = 0; p < 2; ++p)
#pragma unroll
        for (int r = 0; r < 4; ++r)
            li[p][r] = labd[tb + p * 64 + ty * 4 + r];

    const float INF = __int_as_float(0x7f800000);
    float minp[2][4], maxn[2][4];
    int   pidx[2][4], nidx[2][4];
#pragma unroll
    for (int p = 0; p < 2; ++p)
#pragma unroll
        for (int r = 0; r < 4; ++r) {
            minp[p][r] = INF;  pidx[p][r] = 0;
            maxn[p][r] = -INF; nidx[p][r] = 0;
        }

    const float4* As4 = reinterpret_cast<const float4*>(sA);
    const float4* Bs4 = reinterpret_cast<const float4*>(sB);

    for (int jt = 0; jt < NB / BN; ++jt) {
        __syncthreads();  // protect sB / sLab reuse
        const int jbase = jt * BN;
        load_tile(sB, embd + (size_t)jbase * NF, tid);
        if (tid < BN) sLab[tid] = labd[jbase + tid];
        __syncthreads();

        float c[2][2][4][4];
#pragma unroll
        for (int p = 0; p < 2; ++p)
#pragma unroll
            for (int q = 0; q < 2; ++q)
#pragma unroll
                for (int r = 0; r < 4; ++r)
#pragma unroll
                    for (int s = 0; s < 4; ++s)
                        c[p][q][r][s] = 0.0f;

#pragma unroll 8
        for (int k = 0; k < NF; ++k) {
            const int kk = (k >> 2) & 7;
            const float4 a0 = As4[k * 32 + (ty ^ kk)];
            const float4 a1 = As4[k * 32 + 16 + (ty ^ kk)];
            const float4 b0 = Bs4[k * 32 + (tx ^ kk)];
            const float4 b1 = Bs4[k * 32 + 16 + (tx ^ kk)];
            const float av[2][4] = {{a0.x, a0.y, a0.z, a0.w},
                                    {a1.x, a1.y, a1.z, a1.w}};
            const float bv[2][4] = {{b0.x, b0.y, b0.z, b0.w},
                                    {b1.x, b1.y, b1.z, b1.w}};
#pragma unroll
            for (int p = 0; p < 2; ++p)
#pragma unroll
                for (int q = 0; q < 2; ++q)
#pragma unroll
                    for (int r = 0; r < 4; ++r)
#pragma unroll
                        for (int s = 0; s < 4; ++s)
                            c[p][q][r][s] = fmaf(av[p][r], bv[q][s], c[p][q][r][s]);
        }

        // Fused mining epilogue for this 128-col tile.
#pragma unroll
        for (int q = 0; q < 2; ++q)
#pragma unroll
            for (int s = 0; s < 4; ++s) {
                const int jcol = q * 64 + tx * 4 + s;
                const int lj = sLab[jcol];
                const int gj = jbase + jcol;
#pragma unroll
                for (int p = 0; p < 2; ++p)
#pragma unroll
                    for (int r = 0; r < 4; ++r) {
                        const float v = c[p][q][r][s];
                        const int girow = tb + p * 64 + ty * 4 + r;
                        if (lj == li[p][r]) {
                            if (gj != girow && v < minp[p][r]) {
                                minp[p][r] = v; pidx[p][r] = gj;
                            }
                        } else {
                            if (v > maxn[p][r]) {
                                maxn[p][r] = v; nidx[p][r] = gj;
                            }
                        }
                    }
            }
    }

    // Reduce across the 16 column-threads sharing each row (lanes 0-15 / 16-31
    // of each warp), then write dists + gather embeddings.
#pragma unroll
    for (int p = 0; p < 2; ++p)
#pragma unroll
        for (int r = 0; r < 4; ++r) {
            float mp = minp[p][r]; int pi = pidx[p][r];
            float mn = maxn[p][r]; int ni = nidx[p][r];
#pragma unroll
            for (int off = 8; off > 0; off >>= 1) {
                const float vp = __shfl_xor_sync(0xffffffffu, mp, off);
                const int   ip = __shfl_xor_sync(0xffffffffu, pi, off);
                const float vn = __shfl_xor_sync(0xffffffffu, mn, off);
                const int   in_ = __shfl_xor_sync(0xffffffffu, ni, off);
                if (vp < mp) { mp = vp; pi = ip; }
                if (vn > mn) { mn = vn; ni = in_; }
            }
            const int grow = tb + p * 64 + ty * 4 + r;
            const bool has_pos = (mp < INF);
            const size_t go = (size_t)d * NB + grow;
            if (tx == 0) {
                pos_dist[go] = has_pos ? mp : 0.0f;
                neg_dist[go] = has_pos ? mn : 0.0f;
            }
            float4* pdst = reinterpret_cast<float4*>(pos_embed) + go * (NF / 4);
            float4* ndst = reinterpret_cast<float4*>(neg_embed) + go * (NF / 4);
            if (has_pos) {
                const float4* psrc =
                    reinterpret_cast<const float4*>(embd) + (size_t)pi * (NF / 4);
                const float4* nsrc =
                    reinterpret_cast<const float4*>(embd) + (size_t)ni * (NF / 4);
                pdst[tx]      = psrc[tx];
                pdst[tx + 16] = psrc[tx + 16];
                ndst[tx]      = nsrc[tx];
                ndst[tx + 16] = nsrc[tx + 16];
            } else {
                const float4 z = {0.0f, 0.0f, 0.0f, 0.0f};
                pdst[tx] = z; pdst[tx + 16] = z;
                ndst[tx] = z; ndst[tx + 16] = z;
            }
        }
}

extern "C" void kernel_launch(void* const* d_in, const int* in_sizes, int n_in,
                              void* d_out, int out_size) {
    (void)in_sizes; (void)n_in; (void)out_size;
    const float* emb = (const float*)d_in[0];
    const unsigned int* labw = (const unsigned int*)d_in[1];

    float* out = (float*)d_out;
    // Output layout: pos_dist [D,B], neg_dist [D,B], pos_embed [D,B,F], neg_embed [D,B,F]
    float* pos_dist  = out;
    float* neg_dist  = out + (size_t)NDOM * NB;
    float* pos_embed = out + (size_t)2 * NDOM * NB;
    float* neg_embed = pos_embed + (size_t)NDOM * NB * NF;

    convert_labels_kernel<<<1, 256>>>(labw, NDOM * NB);

    cudaFuncSetAttribute(mine_kernel,
                         cudaFuncAttributeMaxDynamicSharedMemorySize, SMEM_BYTES);
    dim3 grid(NB / BM, NDOM);
    mine_kernel<<<grid, NTHREADS, SMEM_BYTES>>>(emb, pos_dist, neg_dist,
                                                pos_embed, neg_embed);
}